// round 17
// baseline (speedup 1.0000x reference)
#include <cuda_runtime.h>
#include <cuda_bf16.h>
#include <math.h>
#include <stdint.h>

#define Bsz  8
#define Ssz  512
#define Hsz  768
#define Lsz  12
#define NHsz 12
#define DHsz 64
#define DFFsz 3072
#define NLsz 19
#define Tsz  (Bsz*Ssz)   // 4096 tokens

// ---------------- scratch ----------------
__device__ float          g_x [Tsz*Hsz];
__device__ float          g_t [Tsz*Hsz];
__device__ __nv_bfloat16  g_xb[Tsz*Hsz];
__device__ __nv_bfloat16  g_qb[Tsz*Hsz];
__device__ __nv_bfloat16  g_kb[Tsz*Hsz];
__device__ __nv_bfloat16  g_vb[Tsz*Hsz];
__device__ __nv_bfloat16  g_cb[Tsz*Hsz];
__device__ __nv_bfloat16  g_hb[Tsz*DFFsz];
__device__ float          g_lg[Tsz*NLsz];
// bf16 weights (pre-converted each launch)
__device__ __nv_bfloat16  g_wq[Lsz*Hsz*Hsz];
__device__ __nv_bfloat16  g_wk[Lsz*Hsz*Hsz];
__device__ __nv_bfloat16  g_wv[Lsz*Hsz*Hsz];
__device__ __nv_bfloat16  g_wo[Lsz*Hsz*Hsz];
__device__ __nv_bfloat16  g_w1[Lsz*Hsz*DFFsz];
__device__ __nv_bfloat16  g_w2[Lsz*DFFsz*Hsz];

// ---------------- fp32 -> bf16 convert (batched over 4 / 2 tensors) ----------------
__device__ __forceinline__ void cvt_body(const float* __restrict__ in,
                                         __nv_bfloat16* __restrict__ out, int n4)
{
    int i = blockIdx.x*blockDim.x + threadIdx.x;
    if (i < n4) {
        float4 f = ((const float4*)in)[i];
        __nv_bfloat162 a = __floats2bfloat162_rn(f.x, f.y);
        __nv_bfloat162 b = __floats2bfloat162_rn(f.z, f.w);
        uint2 o; o.x = *(uint32_t*)&a; o.y = *(uint32_t*)&b;
        ((uint2*)out)[i] = o;
    }
}
__global__ void cvt4_kernel(const float* __restrict__ w0, const float* __restrict__ w1,
                            const float* __restrict__ w2, const float* __restrict__ w3,
                            __nv_bfloat16* __restrict__ o0, __nv_bfloat16* __restrict__ o1,
                            __nv_bfloat16* __restrict__ o2, __nv_bfloat16* __restrict__ o3,
                            int n4)
{
    int z = blockIdx.y;
    const float* in = (z == 0) ? w0 : (z == 1) ? w1 : (z == 2) ? w2 : w3;
    __nv_bfloat16* out = (z == 0) ? o0 : (z == 1) ? o1 : (z == 2) ? o2 : o3;
    cvt_body(in, out, n4);
}
__global__ void cvt2_kernel(const float* __restrict__ w0, const float* __restrict__ w1,
                            __nv_bfloat16* __restrict__ o0, __nv_bfloat16* __restrict__ o1,
                            int n4)
{
    int z = blockIdx.y;
    cvt_body(z ? w1 : w0, z ? o1 : o0, n4);
}

// ---------------- embedding ----------------
__global__ void embed_kernel(const int* __restrict__ ids,
                             const float* __restrict__ tok,
                             const float* __restrict__ pos,
                             float* __restrict__ out)
{
    int t = blockIdx.x;
    int s = t & (Ssz-1);
    int id = ids[t];
    const float* tp = tok + (size_t)id*Hsz;
    const float* pp = pos + (size_t)s*Hsz;
    float* op = out + (size_t)t*Hsz;
    for (int c = threadIdx.x; c < Hsz; c += blockDim.x)
        op[c] = tp[c] + pp[c];
}

// ---------------- layernorm (writes fp32 + bf16) ----------------
__global__ void ln_kernel(const float* __restrict__ in,
                          const float* __restrict__ gamma,
                          const float* __restrict__ beta,
                          float* __restrict__ out,
                          __nv_bfloat16* __restrict__ outb)
{
    __shared__ float sh[32];
    int row = blockIdx.x;
    int tid = threadIdx.x;
    const float* p = in + (size_t)row*Hsz;
    float v0 = p[tid], v1 = p[tid+256], v2 = p[tid+512];
    float s = v0+v1+v2;
    int lane = tid & 31, w = tid >> 5;
    for (int o = 16; o; o >>= 1) s += __shfl_xor_sync(0xffffffffu, s, o);
    if (!lane) sh[w] = s;
    __syncthreads();
    if (w == 0) {
        s = (lane < 8) ? sh[lane] : 0.f;
        for (int o = 4; o; o >>= 1) s += __shfl_xor_sync(0xffffffffu, s, o);
        if (!lane) sh[0] = s;
    }
    __syncthreads();
    float mean = sh[0] * (1.0f/Hsz);
    __syncthreads();
    float d0 = v0-mean, d1 = v1-mean, d2 = v2-mean;
    float q = d0*d0 + d1*d1 + d2*d2;
    for (int o = 16; o; o >>= 1) q += __shfl_xor_sync(0xffffffffu, q, o);
    if (!lane) sh[w] = q;
    __syncthreads();
    if (w == 0) {
        q = (lane < 8) ? sh[lane] : 0.f;
        for (int o = 4; o; o >>= 1) q += __shfl_xor_sync(0xffffffffu, q, o);
        if (!lane) sh[0] = q;
    }
    __syncthreads();
    float var = sh[0] * (1.0f/Hsz);
    float inv = rsqrtf(var + 1e-12f);
    float* op = out + (size_t)row*Hsz;
    __nv_bfloat16* ob = outb + (size_t)row*Hsz;
    float r0 = d0*inv*gamma[tid    ] + beta[tid    ];
    float r1 = d1*inv*gamma[tid+256] + beta[tid+256];
    float r2 = d2*inv*gamma[tid+512] + beta[tid+512];
    op[tid] = r0; op[tid+256] = r1; op[tid+512] = r2;
    ob[tid] = __float2bfloat16(r0);
    ob[tid+256] = __float2bfloat16(r1);
    ob[tid+512] = __float2bfloat16(r2);
}

// ================= MMA / async primitives =================
__device__ __forceinline__ void ldsm_x4(uint32_t (&r)[4], uint32_t addr) {
    asm volatile("ldmatrix.sync.aligned.m8n8.x4.shared.b16 {%0,%1,%2,%3}, [%4];"
        : "=r"(r[0]),"=r"(r[1]),"=r"(r[2]),"=r"(r[3]) : "r"(addr));
}
__device__ __forceinline__ void ldsm_x4_t(uint32_t (&r)[4], uint32_t addr) {
    asm volatile("ldmatrix.sync.aligned.m8n8.x4.trans.shared.b16 {%0,%1,%2,%3}, [%4];"
        : "=r"(r[0]),"=r"(r[1]),"=r"(r[2]),"=r"(r[3]) : "r"(addr));
}
__device__ __forceinline__ void mma16816(float (&c)[4], const uint32_t (&a)[4],
                                         uint32_t b0, uint32_t b1) {
    asm volatile("mma.sync.aligned.m16n8k16.row.col.f32.bf16.bf16.f32 "
        "{%0,%1,%2,%3}, {%4,%5,%6,%7}, {%8,%9}, {%0,%1,%2,%3};"
        : "+f"(c[0]),"+f"(c[1]),"+f"(c[2]),"+f"(c[3])
        : "r"(a[0]),"r"(a[1]),"r"(a[2]),"r"(a[3]), "r"(b0),"r"(b1));
}
__device__ __forceinline__ uint32_t pack_bf16(float x, float y) {
    __nv_bfloat162 h = __floats2bfloat162_rn(x, y);
    return *(uint32_t*)&h;
}
__device__ __forceinline__ void cp16(uint32_t smem, const void* g) {
    asm volatile("cp.async.cg.shared.global [%0], [%1], 16;" :: "r"(smem), "l"(g));
}
__device__ __forceinline__ void cp_commit() { asm volatile("cp.async.commit_group;"); }
__device__ __forceinline__ void cp_wait2()  { asm volatile("cp.async.wait_group 2;"); }
__device__ __forceinline__ void cp_wait1()  { asm volatile("cp.async.wait_group 1;"); }
__device__ __forceinline__ void cp_wait0()  { asm volatile("cp.async.wait_group 0;"); }
__device__ __forceinline__ float fast_gelu(float v) {
    float z = 0.7978845608028654f*(v + 0.044715f*v*v*v);
    float t; asm("tanh.approx.f32 %0, %1;" : "=f"(t) : "f"(z));
    return 0.5f*v*(1.0f + t);
}

// ================= bf16 GEMM, 4-stage cp.async pipeline =================
// C = A[M,K](bf16) @ W[K,N](bf16) + bias; MODE: 1=gelu->bf16, 2=residual->fp32, 3=bias->bf16
#define APAD 40    // A smem row stride (bf16 elems), 80B
#define WPAD 136   // W smem row stride, 272B
#define NSTG 4
#define A_STG (128*APAD)
#define W_STG (32*WPAD)
#define GEMM_SMEM ((NSTG*(A_STG + W_STG))*2)   // 75776 bytes

template<int MODE>
__device__ __forceinline__ void gemm_core(
    const __nv_bfloat16* __restrict__ A, const __nv_bfloat16* __restrict__ W,
    const float* __restrict__ bias, const float* __restrict__ res,
    void* __restrict__ Cout, int N, int K, int m0, int n0)
{
    extern __shared__ __nv_bfloat16 dsm[];
    __nv_bfloat16* As = dsm;                 // NSTG stages of 128*APAD
    __nv_bfloat16* Ws = dsm + NSTG*A_STG;    // NSTG stages of 32*WPAD
    int tid = threadIdx.x;
    int warp = tid >> 5, lane = tid & 31;
    int wm = warp >> 2;
    int wn = warp & 3;
    uint32_t as_base = (uint32_t)__cvta_generic_to_shared(As);
    uint32_t ws_base = (uint32_t)__cvta_generic_to_shared(Ws);

    float acc[4][4][4];
    #pragma unroll
    for (int i = 0; i < 4; i++)
        #pragma unroll
        for (int j = 0; j < 4; j++)
            #pragma unroll
            for (int e = 0; e < 4; e++) acc[i][j][e] = 0.f;

    const int KT = K >> 5;

    // row/col assignments for loads (2 cp16 each for A and W)
    int ar0 = tid >> 2,          ac0 = (tid & 3)*8;
    int ar1 = (tid+256) >> 2,    ac1 = (tid & 3)*8;
    int wr0 = tid >> 4,          wc0 = (tid & 15)*8;
    int wr1 = (tid+256) >> 4,    wc1 = (tid & 15)*8;

    // prologue: stages 0..2
    #pragma unroll
    for (int st = 0; st < NSTG-1; st++) {
        int k0 = st << 5;
        cp16(as_base + (st*A_STG + ar0*APAD + ac0)*2, A + (size_t)(m0 + ar0)*K + k0 + ac0);
        cp16(as_base + (st*A_STG + ar1*APAD + ac1)*2, A + (size_t)(m0 + ar1)*K + k0 + ac1);
        cp16(ws_base + (st*W_STG + wr0*WPAD + wc0)*2, W + (size_t)(k0 + wr0)*N + n0 + wc0);
        cp16(ws_base + (st*W_STG + wr1*WPAD + wc1)*2, W + (size_t)(k0 + wr1)*N + n0 + wc1);
        cp_commit();
    }

    for (int kt = 0; kt < KT; kt++) {
        if (kt < KT-2)      cp_wait2();
        else if (kt == KT-2) cp_wait1();
        else                 cp_wait0();
        __syncthreads();

        int cur = kt & (NSTG-1);
        const __nv_bfloat16* Ac = As + cur*A_STG;
        const __nv_bfloat16* Wc = Ws + cur*W_STG;
        #pragma unroll
        for (int ks = 0; ks < 2; ks++) {
            uint32_t af[4][4];
            #pragma unroll
            for (int i = 0; i < 4; i++) {
                int r = wm*64 + i*16 + (lane & 15);
                int c = ks*16 + (lane >> 4)*8;
                ldsm_x4(af[i], (uint32_t)__cvta_generic_to_shared(Ac + r*APAD + c));
            }
            uint32_t bf[2][4];
            #pragma unroll
            for (int j2 = 0; j2 < 2; j2++) {
                int kk = ks*16 + ((lane>>3)&1)*8 + (lane&7);
                int nn = wn*32 + j2*16 + (lane>>4)*8;
                ldsm_x4_t(bf[j2], (uint32_t)__cvta_generic_to_shared(Wc + kk*WPAD + nn));
            }
            #pragma unroll
            for (int i = 0; i < 4; i++)
                #pragma unroll
                for (int j = 0; j < 4; j++)
                    mma16816(acc[i][j], af[i], bf[j>>1][(j&1)*2], bf[j>>1][(j&1)*2+1]);
        }

        if (kt + NSTG-1 < KT) {
            int st = (kt + NSTG-1) & (NSTG-1);
            int k0 = (kt + NSTG-1) << 5;
            cp16(as_base + (st*A_STG + ar0*APAD + ac0)*2, A + (size_t)(m0 + ar0)*K + k0 + ac0);
            cp16(as_base + (st*A_STG + ar1*APAD + ac1)*2, A + (size_t)(m0 + ar1)*K + k0 + ac1);
            cp16(ws_base + (st*W_STG + wr0*WPAD + wc0)*2, W + (size_t)(k0 + wr0)*N + n0 + wc0);
            cp16(ws_base + (st*W_STG + wr1*WPAD + wc1)*2, W + (size_t)(k0 + wr1)*N + n0 + wc1);
            cp_commit();
        }
    }

    // epilogue
    #pragma unroll
    for (int i = 0; i < 4; i++) {
        int mb = m0 + wm*64 + i*16 + (lane >> 2);
        #pragma unroll
        for (int j = 0; j < 4; j++) {
            int nb = n0 + wn*32 + j*8 + (lane & 3)*2;
            float b0 = bias[nb], b1 = bias[nb+1];
            #pragma unroll
            for (int half = 0; half < 2; half++) {
                int m = mb + half*8;
                float v0 = acc[i][j][half*2]   + b0;
                float v1 = acc[i][j][half*2+1] + b1;
                if (MODE == 1) {
                    v0 = fast_gelu(v0);
                    v1 = fast_gelu(v1);
                } else if (MODE == 2) {
                    float2 r2 = *(const float2*)(res + (size_t)m*N + nb);
                    v0 += r2.x; v1 += r2.y;
                }
                if (MODE == 1 || MODE == 3) {
                    *(__nv_bfloat162*)((__nv_bfloat16*)Cout + (size_t)m*N + nb) =
                        __floats2bfloat162_rn(v0, v1);
                } else {
                    float2 o; o.x = v0; o.y = v1;
                    *(float2*)((float*)Cout + (size_t)m*N + nb) = o;
                }
            }
        }
    }
}

__global__ __launch_bounds__(256,2) void gemm_gelu_kernel(
    const __nv_bfloat16* __restrict__ A, const __nv_bfloat16* __restrict__ W,
    const float* __restrict__ bias, __nv_bfloat16* __restrict__ C, int N, int K)
{
    gemm_core<1>(A, W, bias, nullptr, C, N, K, blockIdx.y*128, blockIdx.x*128);
}
__global__ __launch_bounds__(256,2) void gemm_res_kernel(
    const __nv_bfloat16* __restrict__ A, const __nv_bfloat16* __restrict__ W,
    const float* __restrict__ bias, const float* __restrict__ res,
    float* __restrict__ C, int N, int K)
{
    gemm_core<2>(A, W, bias, res, C, N, K, blockIdx.y*128, blockIdx.x*128);
}
__global__ __launch_bounds__(256,2) void mma_qkv_kernel(
    const __nv_bfloat16* __restrict__ A,
    const __nv_bfloat16* __restrict__ Wq, const __nv_bfloat16* __restrict__ Wk,
    const __nv_bfloat16* __restrict__ Wv,
    const float* __restrict__ bq, const float* __restrict__ bk, const float* __restrict__ bv,
    __nv_bfloat16* __restrict__ q, __nv_bfloat16* __restrict__ k, __nv_bfloat16* __restrict__ v)
{
    int z = blockIdx.z;
    const __nv_bfloat16* W = (z == 0) ? Wq : (z == 1) ? Wk : Wv;
    const float* bb = (z == 0) ? bq : (z == 1) ? bk : bv;
    __nv_bfloat16* C = (z == 0) ? q : (z == 1) ? k : v;
    gemm_core<3>(A, W, bb, nullptr, C, Hsz, Hsz, blockIdx.y*128, blockIdx.x*128);
}

// ================= flash attention (cp.async double-buffered KV) =================
#define FPAD 72

__global__ __launch_bounds__(128) void flash_attn_kernel(
    const __nv_bfloat16* __restrict__ q, const __nv_bfloat16* __restrict__ k,
    const __nv_bfloat16* __restrict__ v, const int* __restrict__ mask,
    __nv_bfloat16* __restrict__ ctx)
{
    __shared__ __nv_bfloat16 Qs[64*FPAD];
    __shared__ __nv_bfloat16 Ks[2][64*FPAD];
    __shared__ __nv_bfloat16 Vs[2][64*FPAD];
    __shared__ float s_bias[Ssz];

    int bh = blockIdx.y;
    int b = bh / NHsz, h = bh % NHsz;
    int i0 = blockIdx.x * 64;
    int tid = threadIdx.x;
    int warp = tid >> 5, lane = tid & 31;
    int g = lane >> 2, t4 = lane & 3;
    uint32_t ks_base = (uint32_t)__cvta_generic_to_shared(&Ks[0][0]);
    uint32_t vs_base = (uint32_t)__cvta_generic_to_shared(&Vs[0][0]);

    #pragma unroll
    for (int it = 0; it < 4; it++) {
        int j = tid + it*128;
        s_bias[j] = mask[b*Ssz + j] ? 0.f : -1e9f;
    }
    #pragma unroll
    for (int it = 0; it < 4; it++) {
        int idx = tid + it*128;
        int r = idx >> 3, c8 = idx & 7;
        *(uint4*)&Qs[r*FPAD + c8*8] =
            *(const uint4*)(q + (size_t)(b*Ssz + i0 + r)*Hsz + h*DHsz + c8*8);
    }
    __syncthreads();

    uint32_t qf[4][4];
    #pragma unroll
    for (int ks = 0; ks < 4; ks++) {
        int r = warp*16 + (lane & 15);
        int c = ks*16 + (lane >> 4)*8;
        ldsm_x4(qf[ks], (uint32_t)__cvta_generic_to_shared(&Qs[r*FPAD + c]));
    }

    #pragma unroll
    for (int it = 0; it < 4; it++) {
        int idx = tid + it*128;
        int r = idx >> 3, c8 = idx & 7;
        size_t goff = (size_t)(b*Ssz + r)*Hsz + h*DHsz + c8*8;
        cp16(ks_base + (r*FPAD + c8*8)*2, k + goff);
        cp16(vs_base + (r*FPAD + c8*8)*2, v + goff);
    }
    cp_commit();

    float oacc[8][4];
    #pragma unroll
    for (int n = 0; n < 8; n++)
        #pragma unroll
        for (int e = 0; e < 4; e++) oacc[n][e] = 0.f;
    float m0v = -1e30f, m1v = -1e30f, l0 = 0.f, l1 = 0.f;

    const int NT = Ssz/64;
    for (int jt = 0; jt < NT; jt++) {
        int cur = jt & 1;
        int j0 = jt*64;
        if (jt + 1 < NT) {
            int st = cur ^ 1;
            int j0n = j0 + 64;
            #pragma unroll
            for (int it = 0; it < 4; it++) {
                int idx = tid + it*128;
                int r = idx >> 3, c8 = idx & 7;
                size_t goff = (size_t)(b*Ssz + j0n + r)*Hsz + h*DHsz + c8*8;
                cp16(ks_base + (st*64*FPAD + r*FPAD + c8*8)*2, k + goff);
                cp16(vs_base + (st*64*FPAD + r*FPAD + c8*8)*2, v + goff);
            }
            cp_commit();
            cp_wait1();
        } else {
            cp_wait0();
        }
        __syncthreads();

        float acc[8][4];
        #pragma unroll
        for (int n = 0; n < 8; n++)
            #pragma unroll
            for (int e = 0; e < 4; e++) acc[n][e] = 0.f;
        #pragma unroll
        for (int jj = 0; jj < 4; jj++) {
            #pragma unroll
            for (int ks = 0; ks < 4; ks++) {
                uint32_t bf[4];
                int r = jj*16 + (lane & 15);
                int c = ks*16 + (lane >> 4)*8;
                ldsm_x4(bf, (uint32_t)__cvta_generic_to_shared(&Ks[cur][r*FPAD + c]));
                mma16816(acc[jj*2  ], qf[ks], bf[0], bf[2]);
                mma16816(acc[jj*2+1], qf[ks], bf[1], bf[3]);
            }
        }

        float p[8][4];
        float mx0 = -1e30f, mx1 = -1e30f;
        #pragma unroll
        for (int n = 0; n < 8; n++) {
            float b0 = s_bias[j0 + n*8 + t4*2];
            float b1 = s_bias[j0 + n*8 + t4*2 + 1];
            p[n][0] = acc[n][0]*0.125f + b0;
            p[n][1] = acc[n][1]*0.125f + b1;
            p[n][2] = acc[n][2]*0.125f + b0;
            p[n][3] = acc[n][3]*0.125f + b1;
            mx0 = fmaxf(mx0, fmaxf(p[n][0], p[n][1]));
            mx1 = fmaxf(mx1, fmaxf(p[n][2], p[n][3]));
        }
        mx0 = fmaxf(mx0, __shfl_xor_sync(0xffffffffu, mx0, 1));
        mx0 = fmaxf(mx0, __shfl_xor_sync(0xffffffffu, mx0, 2));
        mx1 = fmaxf(mx1, __shfl_xor_sync(0xffffffffu, mx1, 1));
        mx1 = fmaxf(mx1, __shfl_xor_sync(0xffffffffu, mx1, 2));
        float mn0 = fmaxf(m0v, mx0);
        float mn1 = fmaxf(m1v, mx1);
        float lt0 = 0.f, lt1 = 0.f;
        #pragma unroll
        for (int n = 0; n < 8; n++) {
            p[n][0] = __expf(p[n][0] - mn0);
            p[n][1] = __expf(p[n][1] - mn0);
            p[n][2] = __expf(p[n][2] - mn1);
            p[n][3] = __expf(p[n][3] - mn1);
            lt0 += p[n][0] + p[n][1];
            lt1 += p[n][2] + p[n][3];
        }
        lt0 += __shfl_xor_sync(0xffffffffu, lt0, 1);
        lt0 += __shfl_xor_sync(0xffffffffu, lt0, 2);
        lt1 += __shfl_xor_sync(0xffffffffu, lt1, 1);
        lt1 += __shfl_xor_sync(0xffffffffu, lt1, 2);
        float sc0 = __expf(m0v - mn0);
        float sc1 = __expf(m1v - mn1);
        l0 = l0*sc0 + lt0;
        l1 = l1*sc1 + lt1;
        m0v = mn0; m1v = mn1;
        #pragma unroll
        for (int n = 0; n < 8; n++) {
            oacc[n][0] *= sc0; oacc[n][1] *= sc0;
            oacc[n][2] *= sc1; oacc[n][3] *= sc1;
        }

        uint32_t pa[4][4];
        #pragma unroll
        for (int c = 0; c < 4; c++) {
            pa[c][0] = pack_bf16(p[2*c  ][0], p[2*c  ][1]);
            pa[c][1] = pack_bf16(p[2*c  ][2], p[2*c  ][3]);
            pa[c][2] = pack_bf16(p[2*c+1][0], p[2*c+1][1]);
            pa[c][3] = pack_bf16(p[2*c+1][2], p[2*c+1][3]);
        }

        #pragma unroll
        for (int db = 0; db < 4; db++) {
            #pragma unroll
            for (int c = 0; c < 4; c++) {
                uint32_t vf[4];
                int kk = c*16 + ((lane>>3)&1)*8 + (lane&7);
                int nn = db*16 + (lane>>4)*8;
                ldsm_x4_t(vf, (uint32_t)__cvta_generic_to_shared(&Vs[cur][kk*FPAD + nn]));
                mma16816(oacc[db*2  ], pa[c], vf[0], vf[1]);
                mma16816(oacc[db*2+1], pa[c], vf[2], vf[3]);
            }
        }
        __syncthreads();
    }

    float inv0 = 1.0f / l0, inv1 = 1.0f / l1;
    #pragma unroll
    for (int n = 0; n < 8; n++) {
        int d = n*8 + t4*2;
        int r0 = i0 + warp*16 + g;
        *(__nv_bfloat162*)(ctx + (size_t)(b*Ssz + r0)*Hsz + h*DHsz + d) =
            __floats2bfloat162_rn(oacc[n][0]*inv0, oacc[n][1]*inv0);
        *(__nv_bfloat162*)(ctx + (size_t)(b*Ssz + r0 + 8)*Hsz + h*DHsz + d) =
            __floats2bfloat162_rn(oacc[n][2]*inv1, oacc[n][3]*inv1);
    }
}

// ---------------- classifier (N=19, SIMT) ----------------
__global__ void sgemm_kernel(const float* __restrict__ A, const float* __restrict__ W,
                             const float* __restrict__ bias, float* __restrict__ C,
                             int M, int N, int K)
{
    __shared__ float As[64][17];
    __shared__ float Ws[16][64];
    int m0 = blockIdx.y * 64;
    int n0 = blockIdx.x * 64;
    int tid = threadIdx.x;
    int ty = tid >> 4, tx = tid & 15;
    float acc[4][4] = {};
    for (int k0 = 0; k0 < K; k0 += 16) {
        #pragma unroll
        for (int i = 0; i < 4; i++) {
            int idx = tid + i*256;
            int r = idx >> 4, c = idx & 15;
            As[r][c] = A[(size_t)(m0+r)*K + (k0+c)];
        }
        #pragma unroll
        for (int i = 0; i < 4; i++) {
            int idx = tid + i*256;
            int r = idx >> 6, c = idx & 63;
            int n = n0 + c;
            Ws[r][c] = (n < N) ? W[(size_t)(k0+r)*N + n] : 0.f;
        }
        __syncthreads();
        #pragma unroll
        for (int kk = 0; kk < 16; kk++) {
            float a[4], b[4];
            #pragma unroll
            for (int i = 0; i < 4; i++) a[i] = As[ty*4+i][kk];
            #pragma unroll
            for (int j = 0; j < 4; j++) b[j] = Ws[kk][tx*4+j];
            #pragma unroll
            for (int i = 0; i < 4; i++)
                #pragma unroll
                for (int j = 0; j < 4; j++)
                    acc[i][j] = fmaf(a[i], b[j], acc[i][j]);
        }
        __syncthreads();
    }
    #pragma unroll
    for (int i = 0; i < 4; i++) {
        int m = m0 + ty*4 + i;
        #pragma unroll
        for (int j = 0; j < 4; j++) {
            int n = n0 + tx*4 + j;
            if (n < N) C[(size_t)m*N + n] = acc[i][j] + bias[n];
        }
    }
}

// ---------------- CRF ----------------
__global__ void crf_kernel(const float* __restrict__ lg, const int* __restrict__ labels,
                           const int* __restrict__ mask, const float* __restrict__ st,
                           const float* __restrict__ en, const float* __restrict__ tr,
                           float* __restrict__ out)
{
    __shared__ float s_tr[NLsz*NLsz];
    __shared__ float s_res[Bsz];
    for (int i = threadIdx.x; i < NLsz*NLsz; i += blockDim.x) s_tr[i] = tr[i];
    __syncthreads();
    int warp = threadIdx.x >> 5, lane = threadIdx.x & 31;
    if (warp < Bsz) {
        int b = warp;
        const int* lab = labels + b*Ssz;
        const int* mk  = mask + b*Ssz;
        const float* lgb = lg + (size_t)b*Ssz*NLsz;
        float part = 0.f; int cnt = 0;
        for (int t = lane; t < Ssz; t += 32) {
            cnt += mk[t];
            if (t >= 1) {
                float mf = (float)mk[t];
                part += (s_tr[lab[t-1]*NLsz + lab[t]] + lgb[t*NLsz + lab[t]]) * mf;
            }
        }
        for (int o = 16; o; o >>= 1) {
            part += __shfl_xor_sync(0xffffffffu, part, o);
            cnt  += __shfl_xor_sync(0xffffffffu, cnt, o);
        }
        float num = 0.f;
        if (lane == 0) {
            int l0 = lab[0];
            num = st[l0] + lgb[l0] + part + en[lab[cnt-1]];
        }
        int j = lane;
        float alpha = (j < NLsz) ? st[j] + lgb[j] : -1e30f;
        for (int t = 1; t < Ssz; t++) {
            float g[NLsz];
            #pragma unroll
            for (int i = 0; i < NLsz; i++)
                g[i] = __shfl_sync(0xffffffffu, alpha, i) + ((j < NLsz) ? s_tr[i*NLsz + j] : 0.f);
            float mv = g[0];
            #pragma unroll
            for (int i = 1; i < NLsz; i++) mv = fmaxf(mv, g[i]);
            float sum = 0.f;
            #pragma unroll
            for (int i = 0; i < NLsz; i++) sum += expf(g[i] - mv);
            float nxt = mv + logf(sum) + ((j < NLsz) ? lgb[t*NLsz + j] : 0.f);
            if (mk[t] > 0 && j < NLsz) alpha = nxt;
        }
        float v = (j < NLsz) ? alpha + en[j] : -1e30f;
        float mv = v;
        for (int o = 16; o; o >>= 1) mv = fmaxf(mv, __shfl_xor_sync(0xffffffffu, mv, o));
        float s = (j < NLsz) ? expf(v - mv) : 0.f;
        for (int o = 16; o; o >>= 1) s += __shfl_xor_sync(0xffffffffu, s, o);
        if (lane == 0) s_res[b] = (mv + logf(s)) - num;
    }
    __syncthreads();
    if (threadIdx.x == 0) {
        float tot = 0.f;
        for (int b = 0; b < Bsz; b++) tot += s_res[b];
        out[0] = tot;
    }
}

// ---------------- host ----------------
extern "C" void kernel_launch(void* const* d_in, const int* in_sizes, int n_in,
                              void* d_out, int out_size)
{
    const int*   input_ids = (const int*)  d_in[0];
    const int*   attn_mask = (const int*)  d_in[1];
    const int*   labels    = (const int*)  d_in[2];
    const float* token_emb = (const float*)d_in[3];
    const float* pos_emb   = (const float*)d_in[4];
    const float* ln_emb_s  = (const float*)d_in[5];
    const float* ln_emb_b  = (const float*)d_in[6];
    const float* Wq        = (const float*)d_in[7];
    const float* bq        = (const float*)d_in[8];
    const float* Wk        = (const float*)d_in[9];
    const float* bk        = (const float*)d_in[10];
    const float* Wv        = (const float*)d_in[11];
    const float* bv        = (const float*)d_in[12];
    const float* Wo        = (const float*)d_in[13];
    const float* bo        = (const float*)d_in[14];
    const float* ln1_s     = (const float*)d_in[15];
    const float* ln1_b     = (const float*)d_in[16];
    const float* W1        = (const float*)d_in[17];
    const float* b1        = (const float*)d_in[18];
    const float* W2        = (const float*)d_in[19];
    const float* b2        = (const float*)d_in[20];
    const float* ln2_s     = (const float*)d_in[21];
    const float* ln2_b     = (const float*)d_in[22];
    const float* cls_W     = (const float*)d_in[23];
    const float* cls_b     = (const float*)d_in[24];
    const float* start_tr  = (const float*)d_in[25];
    const float* end_tr    = (const float*)d_in[26];
    const float* trans     = (const float*)d_in[27];

    float *x, *t, *lg;
    __nv_bfloat16 *xb, *qb, *kb, *vb, *cb, *hb;
    __nv_bfloat16 *wqb, *wkb, *wvb, *wob, *w1b, *w2b;
    { void* p; cudaGetSymbolAddress(&p, g_x);  x  = (float*)p; }
    { void* p; cudaGetSymbolAddress(&p, g_t);  t  = (float*)p; }
    { void* p; cudaGetSymbolAddress(&p, g_lg); lg = (float*)p; }
    { void* p; cudaGetSymbolAddress(&p, g_xb); xb = (__nv_bfloat16*)p; }
    { void* p; cudaGetSymbolAddress(&p, g_qb); qb = (__nv_bfloat16*)p; }
    { void* p; cudaGetSymbolAddress(&p, g_kb); kb = (__nv_bfloat16*)p; }
    { void* p; cudaGetSymbolAddress(&p, g_vb); vb = (__nv_bfloat16*)p; }
    { void* p; cudaGetSymbolAddress(&p, g_cb); cb = (__nv_bfloat16*)p; }
    { void* p; cudaGetSymbolAddress(&p, g_hb); hb = (__nv_bfloat16*)p; }
    { void* p; cudaGetSymbolAddress(&p, g_wq); wqb = (__nv_bfloat16*)p; }
    { void* p; cudaGetSymbolAddress(&p, g_wk); wkb = (__nv_bfloat16*)p; }
    { void* p; cudaGetSymbolAddress(&p, g_wv); wvb = (__nv_bfloat16*)p; }
    { void* p; cudaGetSymbolAddress(&p, g_wo); wob = (__nv_bfloat16*)p; }
    { void* p; cudaGetSymbolAddress(&p, g_w1); w1b = (__nv_bfloat16*)p; }
    { void* p; cudaGetSymbolAddress(&p, g_w2); w2b = (__nv_bfloat16*)p; }

    // allow >48KB dynamic smem on the gemm kernels (idempotent)
    cudaFuncSetAttribute(gemm_gelu_kernel, cudaFuncAttributeMaxDynamicSharedMemorySize, GEMM_SMEM);
    cudaFuncSetAttribute(gemm_res_kernel,  cudaFuncAttributeMaxDynamicSharedMemorySize, GEMM_SMEM);
    cudaFuncSetAttribute(mma_qkv_kernel,   cudaFuncAttributeMaxDynamicSharedMemorySize, GEMM_SMEM);

    // weight pre-conversion (2 batched launches)
    {
        int n4a = Lsz*Hsz*Hsz/4;
        int n4f = Lsz*Hsz*DFFsz/4;
        cvt4_kernel<<<dim3((n4a+255)/256, 4), 256>>>(Wq, Wk, Wv, Wo, wqb, wkb, wvb, wob, n4a);
        cvt2_kernel<<<dim3((n4f+255)/256, 2), 256>>>(W1, W2, w1b, w2b, n4f);
    }

    embed_kernel<<<Tsz, 256>>>(input_ids, token_emb, pos_emb, t);
    ln_kernel<<<Tsz, 256>>>(t, ln_emb_s, ln_emb_b, x, xb);

    for (int l = 0; l < Lsz; l++) {
        const __nv_bfloat16* wq = wqb + (size_t)l*Hsz*Hsz;
        const __nv_bfloat16* wk = wkb + (size_t)l*Hsz*Hsz;
        const __nv_bfloat16* wv = wvb + (size_t)l*Hsz*Hsz;
        const __nv_bfloat16* wo = wob + (size_t)l*Hsz*Hsz;

        mma_qkv_kernel<<<dim3(Hsz/128, Tsz/128, 3), 256, GEMM_SMEM>>>(
            xb, wq, wk, wv, bq + l*Hsz, bk + l*Hsz, bv + l*Hsz, qb, kb, vb);

        flash_attn_kernel<<<dim3(Ssz/64, Bsz*NHsz), 128>>>(qb, kb, vb, attn_mask, cb);

        gemm_res_kernel<<<dim3(Hsz/128, Tsz/128), 256, GEMM_SMEM>>>(
            cb, wo, bo + l*Hsz, x, t, Hsz, Hsz);
        ln_kernel<<<Tsz, 256>>>(t, ln1_s + l*Hsz, ln1_b + l*Hsz, x, xb);

        gemm_gelu_kernel<<<dim3(DFFsz/128, Tsz/128), 256, GEMM_SMEM>>>(
            xb, w1b + (size_t)l*Hsz*DFFsz, b1 + l*DFFsz, hb, DFFsz, Hsz);
        gemm_res_kernel<<<dim3(Hsz/128, Tsz/128), 256, GEMM_SMEM>>>(
            hb, w2b + (size_t)l*DFFsz*Hsz, b2 + l*Hsz, x, t, Hsz, DFFsz);
        ln_kernel<<<Tsz, 256>>>(t, ln2_s + l*Hsz, ln2_b + l*Hsz, x, xb);
    }

    sgemm_kernel<<<dim3(1, Tsz/64), 256>>>(x, cls_W, cls_b, lg, Tsz, NLsz, Hsz);
    crf_kernel<<<1, 256>>>(lg, labels, attn_mask, start_tr, end_tr, trans, (float*)d_out);
}